// round 13
// baseline (speedup 1.0000x reference)
#include <cuda_runtime.h>

#define FULLMASK 0xffffffffu
typedef unsigned long long ull;

// ---------- packed f32x2 helpers (Blackwell sm_103a) ----------
__device__ __forceinline__ ull pk2(float a, float b) {
    ull r;
    asm("mov.b64 %0, {%1, %2};" : "=l"(r) : "f"(a), "f"(b));
    return r;
}
__device__ __forceinline__ float2 upk2(ull v) {
    float2 r;
    asm("mov.b64 {%0, %1}, %2;" : "=f"(r.x), "=f"(r.y) : "l"(v));
    return r;
}
__device__ __forceinline__ ull dup2(float a) { return pk2(a, a); }

__device__ __forceinline__ ull ffma2(ull a, ull b, ull c) {
    ull d;
    asm("fma.rn.f32x2 %0, %1, %2, %3;" : "=l"(d) : "l"(a), "l"(b), "l"(c));
    return d;
}
__device__ __forceinline__ ull add2(ull a, ull b) {
    ull d;
    asm("add.rn.f32x2 %0, %1, %2;" : "=l"(d) : "l"(a), "l"(b));
    return d;
}

// HW tanh: single MUFU.TANH (sm_75+), abs err ~1e-5
__device__ __forceinline__ float tanh_hw(float z) {
    float r;
    asm("tanh.approx.f32 %0, %1;" : "=f"(r) : "f"(z));
    return r;
}

// float->int via magic-number (valid |v| < 2^22): FADD + IADD, no CVT
#define MAGIC_F 12582912.0f          // 1.5 * 2^23
__device__ __forceinline__ int f2i_magic(float v) {
    const float t = v + MAGIC_F;
    return __float_as_int(t) - __float_as_int(MAGIC_F);
}

// warp sum of 2^21-scaled values; returns float sum (still scaled by 2^21)
__device__ __forceinline__ float redux_scaled(float gp_scaled) {
    int si;
    const int gi = f2i_magic(gp_scaled);
    asm("redux.sync.add.s32 %0, %1, 0xffffffff;" : "=r"(si) : "r"(gi));
    float sf;
    asm("cvt.rn.f32.s32 %0, %1;" : "=f"(sf) : "r"(si));
    return sf;
}

// 1024 single-warp CTAs, 2 elements/warp (best-known skeleton).
// R13: element-interleaved hbuf (1 STS.128; each LDS.128 feeds 4 ffma2),
// fused layer-2 loop over both elements (4 split chains each),
// magic-number redux path, HW tanh, off-chain dtn folds.
__global__ void __launch_bounds__(32)
maxwell_ffnn_kernel(const float* __restrict__ x,
                    const float* __restrict__ W1,
                    const float* __restrict__ b1,
                    const float* __restrict__ W2,
                    const float* __restrict__ b2,
                    const float* __restrict__ W3,
                    const float* __restrict__ b3,
                    float* __restrict__ out) {
    __shared__ __align__(16) ulonglong2 hbuf[2][32];   // [parity][lane] = {e0 pair, e1 pair}

    const int l  = threadIdx.x & 31;
    const int jA = l;
    const int jB = l + 32;
    const int u0 = 2 * l;

    const float SC = 2097152.0f;                 // 2^21 (redux scale, magic-safe)
    const float IS = 4.76837158203125e-7f;       // 2^-21

    // ---- loop-invariant weights in registers ----
    const ull c1a = pk2(__ldg(&W1[u0]),      __ldg(&W1[u0 + 1]));
    const ull c1b = pk2(__ldg(&W1[64 + u0]), __ldg(&W1[64 + u0 + 1]));
    const ull cb1 = pk2(__ldg(&b1[u0]),      __ldg(&b1[u0 + 1]));

    ull w2A[32], w2B[32];                        // pair k = rows (2k,2k+1)
#pragma unroll
    for (int k = 0; k < 32; ++k) {
        w2A[k] = pk2(__ldg(&W2[(2 * k) * 64 + jA]),
                     __ldg(&W2[(2 * k + 1) * 64 + jA]));
        w2B[k] = pk2(__ldg(&W2[(2 * k) * 64 + jB]),
                     __ldg(&W2[(2 * k + 1) * 64 + jB]));
    }
    const float b2A = __ldg(&b2[jA]);
    const float b2B = __ldg(&b2[jB]);
    const float w3A = SC * __ldg(&W3[jA]);       // 2^21 * W3
    const float w3B = SC * __ldg(&W3[jB]);
    const float b3v = __ldg(&b3[0]);

    const float2* xp0 = (const float2*)(x + (size_t)(blockIdx.x * 2) * 2048);
    const float2* xp1 = xp0 + 1024;
    float* op0 = out + (size_t)(blockIdx.x * 2) * 1024;
    float* op1 = op0 + 1024;

    float gamma0 = 0.0f, gamma1 = 0.0f;
    float2 xv0 = __ldg(&xp0[0]);
    float2 xv1 = __ldg(&xp1[0]);
    const ull zero2 = pk2(0.0f, 0.0f);

#pragma unroll 2
    for (int t = 0; t < 1024; ++t) {
        const int par = t & 1;
        const float eps0 = xv0.x, dtn0 = xv0.y;
        const float eps1 = xv1.x, dtn1 = xv1.y;
        if (t < 1023) { xv0 = __ldg(&xp0[t + 1]); xv1 = __ldg(&xp1[t + 1]); }

        // off-chain folds
        const float gpre0 = fmaf(dtn0, b3v, gamma0);
        const float gpre1 = fmaf(dtn1, b3v, gamma1);
        const float dIS0  = dtn0 * IS;
        const float dIS1  = dtn1 * IS;

        // ---- layer 1 (both elements) + single STS.128 publish ----
        {
            const ull p0 = ffma2(dup2(gamma0), c1b, ffma2(dup2(eps0), c1a, cb1));
            const ull p1 = ffma2(dup2(gamma1), c1b, ffma2(dup2(eps1), c1a, cb1));
            const float2 q0 = upk2(p0);
            const float2 q1 = upk2(p1);
            hbuf[par][l] = make_ulonglong2(pk2(tanh_hw(q0.x), tanh_hw(q0.y)),
                                           pk2(tanh_hw(q1.x), tanh_hw(q1.y)));
        }
        __syncwarp();

        // ---- layer 2, both elements fused: each LDS.128 feeds 4 ffma2 ----
        ull A0e0 = pk2(b2A, 0.0f), A1e0 = zero2, A2e0 = zero2, A3e0 = zero2;
        ull B0e0 = pk2(b2B, 0.0f), B1e0 = zero2, B2e0 = zero2, B3e0 = zero2;
        ull A0e1 = pk2(b2A, 0.0f), A1e1 = zero2, A2e1 = zero2, A3e1 = zero2;
        ull B0e1 = pk2(b2B, 0.0f), B1e1 = zero2, B2e1 = zero2, B3e1 = zero2;
        {
            const ulonglong2* hp = &hbuf[par][0];
#pragma unroll
            for (int k = 0; k < 8; ++k) {
                const ulonglong2 h0 = hp[4 * k];
                const ulonglong2 h1 = hp[4 * k + 1];
                const ulonglong2 h2 = hp[4 * k + 2];
                const ulonglong2 h3 = hp[4 * k + 3];
                A0e0 = ffma2(h0.x, w2A[4 * k],     A0e0);
                B0e0 = ffma2(h0.x, w2B[4 * k],     B0e0);
                A0e1 = ffma2(h0.y, w2A[4 * k],     A0e1);
                B0e1 = ffma2(h0.y, w2B[4 * k],     B0e1);
                A1e0 = ffma2(h1.x, w2A[4 * k + 1], A1e0);
                B1e0 = ffma2(h1.x, w2B[4 * k + 1], B1e0);
                A1e1 = ffma2(h1.y, w2A[4 * k + 1], A1e1);
                B1e1 = ffma2(h1.y, w2B[4 * k + 1], B1e1);
                A2e0 = ffma2(h2.x, w2A[4 * k + 2], A2e0);
                B2e0 = ffma2(h2.x, w2B[4 * k + 2], B2e0);
                A2e1 = ffma2(h2.y, w2A[4 * k + 2], A2e1);
                B2e1 = ffma2(h2.y, w2B[4 * k + 2], B2e1);
                A3e0 = ffma2(h3.x, w2A[4 * k + 3], A3e0);
                B3e0 = ffma2(h3.x, w2B[4 * k + 3], B3e0);
                A3e1 = ffma2(h3.y, w2A[4 * k + 3], A3e1);
                B3e1 = ffma2(h3.y, w2B[4 * k + 3], B3e1);
            }
        }

        // ---- folds + layer-2 tanh + layer-3 partial (2^21-scaled) ----
        const float2 aA0 = upk2(add2(add2(A0e0, A1e0), add2(A2e0, A3e0)));
        const float2 aB0 = upk2(add2(add2(B0e0, B1e0), add2(B2e0, B3e0)));
        const float2 aA1 = upk2(add2(add2(A0e1, A1e1), add2(A2e1, A3e1)));
        const float2 aB1 = upk2(add2(add2(B0e1, B1e1), add2(B2e1, B3e1)));
        const float gp0 = fmaf(tanh_hw(aA0.x + aA0.y), w3A,
                               tanh_hw(aB0.x + aB0.y) * w3B);
        const float gp1 = fmaf(tanh_hw(aA1.x + aA1.y), w3A,
                               tanh_hw(aB1.x + aB1.y) * w3B);

        // ---- warp sums: magic f2i + redux.s32 + cvt back ----
        const float s0 = redux_scaled(gp0);
        const float s1 = redux_scaled(gp1);

        // ---- gamma update + output ----
        gamma0 = fmaf(dIS0, s0, gpre0);
        gamma1 = fmaf(dIS1, s1, gpre1);

        // sigma = 0.5*eps + 2*(eps - gamma) = 2.5*eps - 2*gamma
        if (l == 0) op0[t] = fmaf(-2.0f, gamma0, 2.5f * eps0);
        if (l == 1) op1[t] = fmaf(-2.0f, gamma1, 2.5f * eps1);
    }
}

extern "C" void kernel_launch(void* const* d_in, const int* in_sizes, int n_in,
                              void* d_out, int out_size) {
    (void)in_sizes; (void)n_in; (void)out_size;
    const float* x  = (const float*)d_in[0];
    const float* W1 = (const float*)d_in[1];
    const float* b1 = (const float*)d_in[2];
    const float* W2 = (const float*)d_in[3];
    const float* b2 = (const float*)d_in[4];
    const float* W3 = (const float*)d_in[5];
    const float* b3 = (const float*)d_in[6];
    float* out = (float*)d_out;

    // 2 elements per warp: 1024 single-warp CTAs (~7/SM, single wave)
    maxwell_ffnn_kernel<<<1024, 32>>>(x, W1, b1, W2, b2, W3, b3, out);
}